// round 7
// baseline (speedup 1.0000x reference)
#include <cuda_runtime.h>
#include <cuda_bf16.h>
#include <cstring>
#include <cstdint>

#define N_SRC1 500000
#define N_DST1 100000
#define E1     1500000
#define N_DST2 20000
#define E2     200000
#define IN_F   128
#define H_F    256
#define N_CLS  47

#define NB1 98   // ceil(N_DST1/1024)
#define NB2 20   // ceil(N_DST2/1024)

// ---------------- scratch (device globals: no allocs allowed) ----------------
__device__ float g_h[(size_t)N_DST1 * H_F];
__device__ float g_hn2[(size_t)N_DST2 * H_F];

__device__ __nv_bfloat16 g_Bhi[256 * 256];   // W1 split hi, [n][k]
__device__ __nv_bfloat16 g_Blo[256 * 256];   // W1 split lo, [n][k]

// zero-initialized at module load; re-zeroed at the end of every launch sequence
__device__ int g_cnt1[N_DST1];
__device__ int g_cnt2[N_DST2];

__device__ int g_row1[N_DST1 + 1];
__device__ int g_cur1[N_DST1];
__device__ int g_eidx1[E1];

__device__ int g_row2[N_DST2 + 1];
__device__ int g_cur2[N_DST2];
__device__ int g_eidx2[E2];

__device__ int g_bsum1[128];
__device__ int g_bsum2[128];
__device__ int g_boff1[128];
__device__ int g_boff2[128];

// ---------------- helpers ----------------
__device__ __forceinline__ uint32_t sptr(const void* p) {
    return (uint32_t)__cvta_generic_to_shared(p);
}

__device__ __forceinline__ void fma2(unsigned long long& d, unsigned long long a,
                                     unsigned long long b) {
    asm("fma.rn.f32x2 %0, %1, %2, %0;" : "+l"(d) : "l"(a), "l"(b));
}
__device__ __forceinline__ unsigned long long dup2(float v) {
    unsigned long long r;
    asm("mov.b64 %0, {%1, %1};" : "=l"(r) : "f"(v));
    return r;
}
__device__ __forceinline__ float2 unpack2(unsigned long long v) {
    float2 f;
    memcpy(&f, &v, 8);
    return f;
}

__device__ __forceinline__ void split8(float4 v0, float4 v1, uint4& hi, uint4& lo) {
    float f[8] = {v0.x, v0.y, v0.z, v0.w, v1.x, v1.y, v1.z, v1.w};
    __nv_bfloat16 h[8], l[8];
    #pragma unroll
    for (int i = 0; i < 8; i++) {
        h[i] = __float2bfloat16_rn(f[i]);
        l[i] = __float2bfloat16_rn(f[i] - __bfloat162float(h[i]));
    }
    memcpy(&hi, h, 16);
    memcpy(&lo, l, 16);
}

__device__ __forceinline__ void split4(float4 v, uint2& hi, uint2& lo) {
    float f[4] = {v.x, v.y, v.z, v.w};
    __nv_bfloat16 h[4], l[4];
    #pragma unroll
    for (int i = 0; i < 4; i++) {
        h[i] = __float2bfloat16_rn(f[i]);
        l[i] = __float2bfloat16_rn(f[i] - __bfloat162float(h[i]));
    }
    memcpy(&hi, h, 8);
    memcpy(&lo, l, 8);
}

__device__ __forceinline__ void ldm_x4(uint32_t* r, uint32_t addr) {
    asm volatile("ldmatrix.sync.aligned.m8n8.x4.shared.b16 {%0,%1,%2,%3}, [%4];"
                 : "=r"(r[0]), "=r"(r[1]), "=r"(r[2]), "=r"(r[3]) : "r"(addr));
}
__device__ __forceinline__ void mma16816(float* d, const uint32_t* a, uint32_t b0, uint32_t b1) {
    asm volatile(
        "mma.sync.aligned.m16n8k16.row.col.f32.bf16.bf16.f32 "
        "{%0,%1,%2,%3}, {%4,%5,%6,%7}, {%8,%9}, {%0,%1,%2,%3};"
        : "+f"(d[0]), "+f"(d[1]), "+f"(d[2]), "+f"(d[3])
        : "r"(a[0]), "r"(a[1]), "r"(a[2]), "r"(a[3]), "r"(b0), "r"(b1));
}

// ---------------- CSR build (counts pre-zeroed: module init / gemm2 tail) ----------------
__global__ void k_count_split(const int* __restrict__ d1, const int* __restrict__ d2,
                              const float* __restrict__ Ws, const float* __restrict__ Wn) {
    int i = blockIdx.x * blockDim.x + threadIdx.x;
    if (i < 256 * 256) {   // W1 split+transpose: [k][n] fp32 -> [n][k] bf16 hi/lo
        int k = i >> 8;
        int n = i & 255;
        float w = (k < 128) ? Ws[k * 256 + n] : Wn[(k - 128) * 256 + n];
        __nv_bfloat16 h = __float2bfloat16_rn(w);
        __nv_bfloat16 l = __float2bfloat16_rn(w - __bfloat162float(h));
        g_Bhi[n * 256 + k] = h;
        g_Blo[n * 256 + k] = l;
    }
    if (i < E1) atomicAdd(&g_cnt1[d1[i]], 1);
    if (i < E2) atomicAdd(&g_cnt2[d2[i]], 1);
}

__global__ void k_scanA() {
    __shared__ int s[1024];
    int b = blockIdx.x;
    const int* cnt; int n; int* bsum; int bb;
    if (b < NB1) { cnt = g_cnt1; n = N_DST1; bsum = g_bsum1; bb = b; }
    else         { cnt = g_cnt2; n = N_DST2; bsum = g_bsum2; bb = b - NB1; }
    int i = bb * 1024 + threadIdx.x;
    int v = (i < n) ? cnt[i] : 0;
    s[threadIdx.x] = v;
    __syncthreads();
    #pragma unroll
    for (int off = 512; off > 0; off >>= 1) {
        if (threadIdx.x < off) s[threadIdx.x] += s[threadIdx.x + off];
        __syncthreads();
    }
    if (threadIdx.x == 0) bsum[bb] = s[0];
}

__global__ void k_scanB() {
    __shared__ int s1[128];
    __shared__ int s2[128];
    int t = threadIdx.x;
    if (t < 128) s1[t] = (t < NB1) ? g_bsum1[t] : 0;
    else         { int u = t - 128; s2[u] = (u < NB2) ? g_bsum2[u] : 0; }
    __syncthreads();
    #pragma unroll
    for (int off = 1; off < 128; off <<= 1) {
        int v;
        if (t < 128) v = (t >= off) ? s1[t - off] : 0;
        else         { int u = t - 128; v = (u >= off) ? s2[u - off] : 0; }
        __syncthreads();
        if (t < 128) s1[t] += v;
        else         s2[t - 128] += v;
        __syncthreads();
    }
    if (t < 128) { if (t < NB1) g_boff1[t] = (t ? s1[t - 1] : 0); }
    else         { int u = t - 128; if (u < NB2) g_boff2[u] = (u ? s2[u - 1] : 0); }
}

__global__ void k_scanC() {
    __shared__ int s[1024];
    int b = blockIdx.x;
    const int* cnt; int n; int* row; int* cur; int boff; int bb; int etot;
    if (b < NB1) { cnt = g_cnt1; n = N_DST1; row = g_row1; cur = g_cur1; bb = b;       boff = g_boff1[bb]; etot = E1; }
    else         { cnt = g_cnt2; n = N_DST2; row = g_row2; cur = g_cur2; bb = b - NB1; boff = g_boff2[bb]; etot = E2; }
    int t = threadIdx.x;
    int i = bb * 1024 + t;
    int v = (i < n) ? cnt[i] : 0;
    s[t] = v;
    __syncthreads();
    #pragma unroll
    for (int off = 1; off < 1024; off <<= 1) {
        int u = (t >= off) ? s[t - off] : 0;
        __syncthreads();
        s[t] += u;
        __syncthreads();
    }
    int excl = boff + s[t] - v;
    if (i < n) { row[i] = excl; cur[i] = excl; }
    if (i == n - 1) row[n] = etot;
}

__global__ void k_fill(const int* __restrict__ s1, const int* __restrict__ d1,
                       const int* __restrict__ s2, const int* __restrict__ d2) {
    int i = blockIdx.x * blockDim.x + threadIdx.x;
    if (i < E1) {
        int p = atomicAdd(&g_cur1[d1[i]], 1);
        g_eidx1[p] = s1[i];
    }
    if (i < E2) {
        int p = atomicAdd(&g_cur2[d2[i]], 1);
        g_eidx2[p] = s2[i];
    }
}

// ---------------- FUSED layer-1: per-block aggregation + tensor-core GEMM ----------------
// Block = 128 dst rows x full N=256. Prologue aggregates hn1 for its rows straight
// into bf16 hi/lo smem A-tiles; mainloop: kc<8 A from x (gmem), kc>=8 A from smem.
// smem layout (bf16 elems): AfullHi[128*136], AfullLo[128*136],
//                           AxHi[128*24], AxLo[128*24], BHi[256*24], BLo[256*24]
#define PF 136
#define APITCH 24
#define OFF_AFHI 0
#define OFF_AFLO (128 * PF)
#define OFF_AXHI (2 * 128 * PF)
#define OFF_AXLO (2 * 128 * PF + 128 * APITCH)
#define OFF_BHI  (2 * 128 * PF + 2 * 128 * APITCH)
#define OFF_BLO  (2 * 128 * PF + 2 * 128 * APITCH + 256 * APITCH)
#define SMEM_ELEMS (2 * 128 * PF + 2 * 128 * APITCH + 2 * 256 * APITCH)
#define SMEM_BYTES (SMEM_ELEMS * 2)

__global__ __launch_bounds__(256, 1) void k_fused1(const float* __restrict__ x,
                                                   const float* __restrict__ b1) {
    extern __shared__ __nv_bfloat16 sm[];
    __nv_bfloat16* sAfHi = sm + OFF_AFHI;
    __nv_bfloat16* sAfLo = sm + OFF_AFLO;
    __nv_bfloat16* sAxHi = sm + OFF_AXHI;
    __nv_bfloat16* sAxLo = sm + OFF_AXLO;
    __nv_bfloat16* sBHi  = sm + OFF_BHI;
    __nv_bfloat16* sBLo  = sm + OFF_BLO;

    int t = threadIdx.x;
    int lane = t & 31;
    int wid = t >> 5;
    int m0 = blockIdx.x * 128;

    // ---- prologue: aggregate 16 rows per warp into sAfull (bf16 hi/lo) ----
    {
        const float4* x4 = (const float4*)x;
        for (int rr = 0; rr < 16; rr++) {
            int r = wid * 16 + rr;
            int gr = m0 + r;
            float4 acc = make_float4(0.f, 0.f, 0.f, 0.f);
            if (gr < N_DST1) {
                int e0 = g_row1[gr], e1 = g_row1[gr + 1];
                int e = e0;
                for (; e + 3 < e1; e += 4) {
                    int sa = g_eidx1[e];
                    int sb = g_eidx1[e + 1];
                    int sc = g_eidx1[e + 2];
                    int sd = g_eidx1[e + 3];
                    float4 va = __ldg(&x4[(size_t)sa * 32 + lane]);
                    float4 vb = __ldg(&x4[(size_t)sb * 32 + lane]);
                    float4 vc = __ldg(&x4[(size_t)sc * 32 + lane]);
                    float4 vd = __ldg(&x4[(size_t)sd * 32 + lane]);
                    acc.x += (va.x + vb.x) + (vc.x + vd.x);
                    acc.y += (va.y + vb.y) + (vc.y + vd.y);
                    acc.z += (va.z + vb.z) + (vc.z + vd.z);
                    acc.w += (va.w + vb.w) + (vc.w + vd.w);
                }
                for (; e < e1; e++) {
                    int sa = g_eidx1[e];
                    float4 va = __ldg(&x4[(size_t)sa * 32 + lane]);
                    acc.x += va.x; acc.y += va.y; acc.z += va.z; acc.w += va.w;
                }
                float inv = 1.0f / fmaxf((float)(e1 - e0), 1.0f);
                acc.x *= inv; acc.y *= inv; acc.z *= inv; acc.w *= inv;
            }
            uint2 hi, lo;
            split4(acc, hi, lo);
            *(uint2*)&sAfHi[r * PF + lane * 4] = hi;
            *(uint2*)&sAfLo[r * PF + lane * 4] = lo;
        }
    }
    __syncthreads();

    // ---- GEMM ----
    int wm = (wid & 3) * 32;
    int wn = (wid >> 2) * 128;

    float acc[2][16][4];
    #pragma unroll
    for (int i = 0; i < 2; i++)
        #pragma unroll
        for (int j = 0; j < 16; j++)
            #pragma unroll
            for (int q = 0; q < 4; q++) acc[i][j][q] = 0.f;

    int lrow = t >> 1;        // x A-tile: 0..127
    int lq   = (t & 1) << 3;
    int grow = m0 + lrow;

    int a_r = (lane & 15);
    int a_c = (lane >> 4) << 3;
    int b_r = (lane & 7) + ((lane >> 4) << 3);
    int b_c = ((lane >> 3) & 1) << 3;

    uint32_t axHi = sptr(sAxHi), axLo = sptr(sAxLo);
    uint32_t afHi = sptr(sAfHi), afLo = sptr(sAfLo);
    uint32_t bHi = sptr(sBHi), bLo = sptr(sBLo);

    float4 pA0, pA1;
    uint4 pBh0, pBh1, pBl0, pBl1;

    auto ldA = [&](int kc) {   // only for kc<8 (x part)
        if (grow < N_DST1) {
            const float* p = x + (size_t)grow * IN_F + kc * 16 + lq;
            pA0 = *(const float4*)p;
            pA1 = *(const float4*)(p + 4);
        } else {
            pA0 = make_float4(0.f, 0.f, 0.f, 0.f);
            pA1 = make_float4(0.f, 0.f, 0.f, 0.f);
        }
    };
    auto ldB = [&](int kc) {   // row t (0..255), 16 k = 2 uint4 each
        size_t off = (size_t)t * 256 + kc * 16;
        pBh0 = *(const uint4*)(g_Bhi + off);
        pBh1 = *(const uint4*)(g_Bhi + off + 8);
        pBl0 = *(const uint4*)(g_Blo + off);
        pBl1 = *(const uint4*)(g_Blo + off + 8);
    };
    auto stsA = [&]() {
        uint4 hi, lo;
        split8(pA0, pA1, hi, lo);
        *(uint4*)&sAxHi[lrow * APITCH + lq] = hi;
        *(uint4*)&sAxLo[lrow * APITCH + lq] = lo;
    };
    auto stsB = [&]() {
        *(uint4*)&sBHi[t * APITCH + 0] = pBh0;
        *(uint4*)&sBHi[t * APITCH + 8] = pBh1;
        *(uint4*)&sBLo[t * APITCH + 0] = pBl0;
        *(uint4*)&sBLo[t * APITCH + 8] = pBl1;
    };
    auto pass = [&](uint32_t abase, int apitch, int acol, uint32_t bbase) {
        uint32_t a[2][4];
        #pragma unroll
        for (int mf = 0; mf < 2; mf++)
            ldm_x4(a[mf], abase + ((wm + mf * 16 + a_r) * apitch + acol + a_c) * 2);
        #pragma unroll
        for (int p = 0; p < 8; p++) {
            uint32_t bb[4];
            ldm_x4(bb, bbase + ((wn + p * 16 + b_r) * APITCH + b_c) * 2);
            #pragma unroll
            for (int mf = 0; mf < 2; mf++) {
                mma16816(acc[mf][p * 2],     a[mf], bb[0], bb[1]);
                mma16816(acc[mf][p * 2 + 1], a[mf], bb[2], bb[3]);
            }
        }
    };

    ldA(0);
    ldB(0);
    for (int kc = 0; kc < 16; kc++) {
        if (kc < 8) stsA();
        stsB();
        __syncthreads();
        if (kc < 15) {
            if (kc + 1 < 8) ldA(kc + 1);
            ldB(kc + 1);
        }
        if (kc < 8) {
            pass(axHi, APITCH, 0, bHi);
            pass(axLo, APITCH, 0, bHi);
            pass(axHi, APITCH, 0, bLo);
        } else {
            int acol = (kc - 8) * 16;
            pass(afHi, PF, acol, bHi);
            pass(afLo, PF, acol, bHi);
            pass(afHi, PF, acol, bLo);
        }
        __syncthreads();
    }

    // ---- epilogue: bias + relu -> g_h ----
    #pragma unroll
    for (int mf = 0; mf < 2; mf++) {
        int gr0 = m0 + wm + mf * 16 + (lane >> 2);
        int gr1 = gr0 + 8;
        #pragma unroll
        for (int nf = 0; nf < 16; nf++) {
            int gn = wn + nf * 8 + ((lane & 3) << 1);
            float bx = b1[gn];
            float by = b1[gn + 1];
            float* d = acc[mf][nf];
            if (gr0 < N_DST1)
                *(float2*)&g_h[(size_t)gr0 * H_F + gn] =
                    make_float2(fmaxf(d[0] + bx, 0.f), fmaxf(d[1] + by, 0.f));
            if (gr1 < N_DST1)
                *(float2*)&g_h[(size_t)gr1 * H_F + gn] =
                    make_float2(fmaxf(d[2] + bx, 0.f), fmaxf(d[3] + by, 0.f));
        }
    }
}

// ---------------- layer-2 aggregation (warp per dst node) ----------------
__global__ void k_agg2() {
    int w = (blockIdx.x * blockDim.x + threadIdx.x) >> 5;
    int lane = threadIdx.x & 31;
    if (w >= N_DST2) return;
    const float4* h4 = (const float4*)g_h;
    int e0 = g_row2[w], e1 = g_row2[w + 1];
    float4 a0 = make_float4(0.f, 0.f, 0.f, 0.f);
    float4 a1 = make_float4(0.f, 0.f, 0.f, 0.f);
    for (int e = e0; e < e1; e++) {
        int s = g_eidx2[e];
        float4 v0 = __ldg(&h4[(size_t)s * 64 + lane]);
        float4 v1 = __ldg(&h4[(size_t)s * 64 + lane + 32]);
        a0.x += v0.x; a0.y += v0.y; a0.z += v0.z; a0.w += v0.w;
        a1.x += v1.x; a1.y += v1.y; a1.z += v1.z; a1.w += v1.w;
    }
    float inv = 1.0f / fmaxf((float)(e1 - e0), 1.0f);
    a0.x *= inv; a0.y *= inv; a0.z *= inv; a0.w *= inv;
    a1.x *= inv; a1.y *= inv; a1.z *= inv; a1.w *= inv;
    ((float4*)g_hn2)[(size_t)w * 64 + lane] = a0;
    ((float4*)g_hn2)[(size_t)w * 64 + lane + 32] = a1;
}

// ---------------- layer-2 GEMM + count-rezero tail ----------------
__global__ __launch_bounds__(256) void k_gemm2(const float* __restrict__ Ws2,
                                               const float* __restrict__ Wn2,
                                               const float* __restrict__ b2,
                                               float* __restrict__ out) {
    __shared__ float As[32][128];
    __shared__ float Bs[32][48];
    int t = threadIdx.x;
    int m0 = blockIdx.x * 128;
    int r0 = (t >> 3) * 4;
    int c0 = (t & 7) * 6;

    unsigned long long acc[4][3];
    #pragma unroll
    for (int i = 0; i < 4; i++)
        #pragma unroll
        for (int j = 0; j < 3; j++) acc[i][j] = 0ull;

    for (int kt = 0; kt < 16; kt++) {
        const float* Ab = (kt < 8) ? g_h : g_hn2;
        const float* Bb = (kt < 8) ? Ws2 : Wn2;
        int koff = (kt < 8) ? kt * 32 : (kt - 8) * 32;

        {
            int row = t >> 1;
            int grow = m0 + row;
            #pragma unroll
            for (int j = 0; j < 4; j++) {
                int kq = (t & 1) * 16 + j * 4;
                float4 v = make_float4(0.f, 0.f, 0.f, 0.f);
                if (grow < N_DST2) v = *(const float4*)(Ab + (size_t)grow * H_F + koff + kq);
                As[kq + 0][row] = v.x;
                As[kq + 1][row] = v.y;
                As[kq + 2][row] = v.z;
                As[kq + 3][row] = v.w;
            }
        }
        for (int l = t; l < 32 * N_CLS; l += 256) {
            int k = l / N_CLS;
            int c = l - k * N_CLS;
            Bs[k][c] = Bb[(size_t)(koff + k) * N_CLS + c];
        }
        __syncthreads();
        #pragma unroll
        for (int k = 0; k < 32; k++) {
            float4 a = *(const float4*)&As[k][r0];
            float av[4] = {a.x, a.y, a.z, a.w};
            unsigned long long bp[3];
            bp[0] = *(const unsigned long long*)&Bs[k][c0];
            bp[1] = *(const unsigned long long*)&Bs[k][c0 + 2];
            bp[2] = *(const unsigned long long*)&Bs[k][c0 + 4];
            #pragma unroll
            for (int i = 0; i < 4; i++) {
                unsigned long long ad = dup2(av[i]);
                #pragma unroll
                for (int j = 0; j < 3; j++) fma2(acc[i][j], ad, bp[j]);
            }
        }
        __syncthreads();
    }

    #pragma unroll
    for (int i = 0; i < 4; i++) {
        int row = m0 + r0 + i;
        if (row < N_DST2) {
            #pragma unroll
            for (int j = 0; j < 3; j++) {
                float2 v = unpack2(acc[i][j]);
                int c = c0 + 2 * j;
                if (c < N_CLS)     out[(size_t)row * N_CLS + c]     = v.x + b2[c];
                if (c + 1 < N_CLS) out[(size_t)row * N_CLS + c + 1] = v.y + b2[c + 1];
            }
        }
    }

    // rezero counts for the next graph replay (grid-stride)
    int stride = gridDim.x * blockDim.x;
    for (int i = blockIdx.x * blockDim.x + t; i < N_DST1; i += stride) g_cnt1[i] = 0;
    for (int i = blockIdx.x * blockDim.x + t; i < N_DST2; i += stride) g_cnt2[i] = 0;
}

// ---------------- launch ----------------
extern "C" void kernel_launch(void* const* d_in, const int* in_sizes, int n_in,
                              void* d_out, int out_size) {
    const float* x   = (const float*)d_in[0];
    const float* Ws1 = (const float*)d_in[1];
    const float* Wn1 = (const float*)d_in[2];
    const float* b1  = (const float*)d_in[3];
    const float* Ws2 = (const float*)d_in[4];
    const float* Wn2 = (const float*)d_in[5];
    const float* b2  = (const float*)d_in[6];
    const int* src1  = (const int*)d_in[7];
    const int* dst1  = (const int*)d_in[8];
    const int* src2  = (const int*)d_in[9];
    const int* dst2  = (const int*)d_in[10];
    float* out = (float*)d_out;

    static bool attr_set = false;
    if (!attr_set) {
        cudaFuncSetAttribute(k_fused1, cudaFuncAttributeMaxDynamicSharedMemorySize, SMEM_BYTES);
        attr_set = true;
    }

    k_count_split<<<(E1 + 255) / 256, 256>>>(dst1, dst2, Ws1, Wn1);   // 0
    k_scanA<<<NB1 + NB2, 1024>>>();                                   // 1
    k_scanB<<<1, 256>>>();                                            // 2
    k_scanC<<<NB1 + NB2, 1024>>>();                                   // 3
    k_fill<<<(E1 + 255) / 256, 256>>>(src1, dst1, src2, dst2);        // 4
    k_fused1<<<(N_DST1 + 127) / 128, 256, SMEM_BYTES>>>(x, b1);       // 5  <- ncu -s 5 -c 1
    k_agg2<<<(N_DST2 * 32 + 255) / 256, 256>>>();                     // 6
    k_gemm2<<<(N_DST2 + 127) / 128, 256>>>(Ws2, Wn2, b2, out);        // 7
}

// round 8
// speedup vs baseline: 1.3318x; 1.3318x over previous
#include <cuda_runtime.h>
#include <cuda_bf16.h>
#include <cstring>
#include <cstdint>

#define N_SRC1 500000
#define N_DST1 100000
#define E1     1500000
#define N_DST2 20000
#define E2     200000
#define IN_F   128
#define H_F    256
#define N_CLS  47

#define NB1 98   // ceil(N_DST1/1024)
#define NB2 20   // ceil(N_DST2/1024)

// ---------------- scratch (device globals: no allocs allowed) ----------------
__device__ float g_hn1[(size_t)N_DST1 * IN_F];
__device__ float g_h[(size_t)N_DST1 * H_F];
__device__ float g_hn2[(size_t)N_DST2 * H_F];

__device__ __nv_bfloat16 g_Bhi[256 * 256];   // W1 split hi, [n][k]
__device__ __nv_bfloat16 g_Blo[256 * 256];   // W1 split lo, [n][k]

// zero-initialized at module load; re-zeroed by gemm2's tail every replay
__device__ int g_cnt1[N_DST1];
__device__ int g_cnt2[N_DST2];

__device__ int g_row1[N_DST1 + 1];
__device__ int g_cur1[N_DST1];
__device__ int g_eidx1[E1];

__device__ int g_row2[N_DST2 + 1];
__device__ int g_cur2[N_DST2];
__device__ int g_eidx2[E2];

__device__ int g_bsum1[128];
__device__ int g_bsum2[128];
__device__ int g_boff1[128];
__device__ int g_boff2[128];

// ---------------- helpers ----------------
__device__ __forceinline__ uint32_t sptr(const void* p) {
    return (uint32_t)__cvta_generic_to_shared(p);
}

__device__ __forceinline__ void fma2(unsigned long long& d, unsigned long long a,
                                     unsigned long long b) {
    asm("fma.rn.f32x2 %0, %1, %2, %0;" : "+l"(d) : "l"(a), "l"(b));
}
__device__ __forceinline__ unsigned long long dup2(float v) {
    unsigned long long r;
    asm("mov.b64 %0, {%1, %1};" : "=l"(r) : "f"(v));
    return r;
}
__device__ __forceinline__ float2 unpack2(unsigned long long v) {
    float2 f;
    memcpy(&f, &v, 8);
    return f;
}

__device__ __forceinline__ void split8(float4 v0, float4 v1, uint4& hi, uint4& lo) {
    float f[8] = {v0.x, v0.y, v0.z, v0.w, v1.x, v1.y, v1.z, v1.w};
    __nv_bfloat16 h[8], l[8];
    #pragma unroll
    for (int i = 0; i < 8; i++) {
        h[i] = __float2bfloat16_rn(f[i]);
        l[i] = __float2bfloat16_rn(f[i] - __bfloat162float(h[i]));
    }
    memcpy(&hi, h, 16);
    memcpy(&lo, l, 16);
}

__device__ __forceinline__ void ldm_x4(uint32_t* r, uint32_t addr) {
    asm volatile("ldmatrix.sync.aligned.m8n8.x4.shared.b16 {%0,%1,%2,%3}, [%4];"
                 : "=r"(r[0]), "=r"(r[1]), "=r"(r[2]), "=r"(r[3]) : "r"(addr));
}
__device__ __forceinline__ void mma16816(float* d, const uint32_t* a, uint32_t b0, uint32_t b1) {
    asm volatile(
        "mma.sync.aligned.m16n8k16.row.col.f32.bf16.bf16.f32 "
        "{%0,%1,%2,%3}, {%4,%5,%6,%7}, {%8,%9}, {%0,%1,%2,%3};"
        : "+f"(d[0]), "+f"(d[1]), "+f"(d[2]), "+f"(d[3])
        : "r"(a[0]), "r"(a[1]), "r"(a[2]), "r"(a[3]), "r"(b0), "r"(b1));
}

// ---------------- CSR build + W1 split (counts pre-zeroed) ----------------
__global__ void k_count_split(const int* __restrict__ d1, const int* __restrict__ d2,
                              const float* __restrict__ Ws, const float* __restrict__ Wn) {
    int i = blockIdx.x * blockDim.x + threadIdx.x;
    if (i < 256 * 256) {   // W1 split+transpose: [k][n] fp32 -> [n][k] bf16 hi/lo
        int k = i >> 8;
        int n = i & 255;
        float w = (k < 128) ? Ws[k * 256 + n] : Wn[(k - 128) * 256 + n];
        __nv_bfloat16 h = __float2bfloat16_rn(w);
        __nv_bfloat16 l = __float2bfloat16_rn(w - __bfloat162float(h));
        g_Bhi[n * 256 + k] = h;
        g_Blo[n * 256 + k] = l;
    }
    if (i < E1) atomicAdd(&g_cnt1[d1[i]], 1);
    if (i < E2) atomicAdd(&g_cnt2[d2[i]], 1);
}

__global__ void k_scanA() {
    __shared__ int s[1024];
    int b = blockIdx.x;
    const int* cnt; int n; int* bsum; int bb;
    if (b < NB1) { cnt = g_cnt1; n = N_DST1; bsum = g_bsum1; bb = b; }
    else         { cnt = g_cnt2; n = N_DST2; bsum = g_bsum2; bb = b - NB1; }
    int i = bb * 1024 + threadIdx.x;
    int v = (i < n) ? cnt[i] : 0;
    s[threadIdx.x] = v;
    __syncthreads();
    #pragma unroll
    for (int off = 512; off > 0; off >>= 1) {
        if (threadIdx.x < off) s[threadIdx.x] += s[threadIdx.x + off];
        __syncthreads();
    }
    if (threadIdx.x == 0) bsum[bb] = s[0];
}

__global__ void k_scanB() {
    __shared__ int s1[128];
    __shared__ int s2[128];
    int t = threadIdx.x;
    if (t < 128) s1[t] = (t < NB1) ? g_bsum1[t] : 0;
    else         { int u = t - 128; s2[u] = (u < NB2) ? g_bsum2[u] : 0; }
    __syncthreads();
    #pragma unroll
    for (int off = 1; off < 128; off <<= 1) {
        int v;
        if (t < 128) v = (t >= off) ? s1[t - off] : 0;
        else         { int u = t - 128; v = (u >= off) ? s2[u - off] : 0; }
        __syncthreads();
        if (t < 128) s1[t] += v;
        else         s2[t - 128] += v;
        __syncthreads();
    }
    if (t < 128) { if (t < NB1) g_boff1[t] = (t ? s1[t - 1] : 0); }
    else         { int u = t - 128; if (u < NB2) g_boff2[u] = (u ? s2[u - 1] : 0); }
}

__global__ void k_scanC() {
    __shared__ int s[1024];
    int b = blockIdx.x;
    const int* cnt; int n; int* row; int* cur; int boff; int bb; int etot;
    if (b < NB1) { cnt = g_cnt1; n = N_DST1; row = g_row1; cur = g_cur1; bb = b;       boff = g_boff1[bb]; etot = E1; }
    else         { cnt = g_cnt2; n = N_DST2; row = g_row2; cur = g_cur2; bb = b - NB1; boff = g_boff2[bb]; etot = E2; }
    int t = threadIdx.x;
    int i = bb * 1024 + t;
    int v = (i < n) ? cnt[i] : 0;
    s[t] = v;
    __syncthreads();
    #pragma unroll
    for (int off = 1; off < 1024; off <<= 1) {
        int u = (t >= off) ? s[t - off] : 0;
        __syncthreads();
        s[t] += u;
        __syncthreads();
    }
    int excl = boff + s[t] - v;
    if (i < n) { row[i] = excl; cur[i] = excl; }
    if (i == n - 1) row[n] = etot;
}

__global__ void k_fill(const int* __restrict__ s1, const int* __restrict__ d1,
                       const int* __restrict__ s2, const int* __restrict__ d2) {
    int i = blockIdx.x * blockDim.x + threadIdx.x;
    if (i < E1) {
        int p = atomicAdd(&g_cur1[d1[i]], 1);
        g_eidx1[p] = s1[i];
    }
    if (i < E2) {
        int p = atomicAdd(&g_cur2[d2[i]], 1);
        g_eidx2[p] = s2[i];
    }
}

// ---------------- aggregation (warp per dst node) ----------------
__global__ void k_agg1(const float4* __restrict__ x4) {
    int w = (blockIdx.x * blockDim.x + threadIdx.x) >> 5;
    int lane = threadIdx.x & 31;
    if (w >= N_DST1) return;
    int e0 = g_row1[w], e1 = g_row1[w + 1];
    float4 acc = make_float4(0.f, 0.f, 0.f, 0.f);
    int e = e0;
    for (; e + 3 < e1; e += 4) {
        int sa = g_eidx1[e];
        int sb = g_eidx1[e + 1];
        int sc = g_eidx1[e + 2];
        int sd = g_eidx1[e + 3];
        float4 va = __ldg(&x4[(size_t)sa * 32 + lane]);
        float4 vb = __ldg(&x4[(size_t)sb * 32 + lane]);
        float4 vc = __ldg(&x4[(size_t)sc * 32 + lane]);
        float4 vd = __ldg(&x4[(size_t)sd * 32 + lane]);
        acc.x += (va.x + vb.x) + (vc.x + vd.x);
        acc.y += (va.y + vb.y) + (vc.y + vd.y);
        acc.z += (va.z + vb.z) + (vc.z + vd.z);
        acc.w += (va.w + vb.w) + (vc.w + vd.w);
    }
    for (; e < e1; e++) {
        int sa = g_eidx1[e];
        float4 va = __ldg(&x4[(size_t)sa * 32 + lane]);
        acc.x += va.x; acc.y += va.y; acc.z += va.z; acc.w += va.w;
    }
    float inv = 1.0f / fmaxf((float)(e1 - e0), 1.0f);
    acc.x *= inv; acc.y *= inv; acc.z *= inv; acc.w *= inv;
    ((float4*)g_hn1)[(size_t)w * 32 + lane] = acc;
}

__global__ void k_agg2() {
    int w = (blockIdx.x * blockDim.x + threadIdx.x) >> 5;
    int lane = threadIdx.x & 31;
    if (w >= N_DST2) return;
    const float4* h4 = (const float4*)g_h;
    int e0 = g_row2[w], e1 = g_row2[w + 1];
    float4 a0 = make_float4(0.f, 0.f, 0.f, 0.f);
    float4 a1 = make_float4(0.f, 0.f, 0.f, 0.f);
    for (int e = e0; e < e1; e++) {
        int s = g_eidx2[e];
        float4 v0 = __ldg(&h4[(size_t)s * 64 + lane]);
        float4 v1 = __ldg(&h4[(size_t)s * 64 + lane + 32]);
        a0.x += v0.x; a0.y += v0.y; a0.z += v0.z; a0.w += v0.w;
        a1.x += v1.x; a1.y += v1.y; a1.z += v1.z; a1.w += v1.w;
    }
    float inv = 1.0f / fmaxf((float)(e1 - e0), 1.0f);
    a0.x *= inv; a0.y *= inv; a0.z *= inv; a0.w *= inv;
    a1.x *= inv; a1.y *= inv; a1.z *= inv; a1.w *= inv;
    ((float4*)g_hn2)[(size_t)w * 64 + lane] = a0;
    ((float4*)g_hn2)[(size_t)w * 64 + lane + 32] = a1;
}

// ---------------- layer-1 GEMM (tensor cores, bf16 hi/lo split, double-buffered) ----------------
// C[100000,256] = relu([x|hn1] @ W' + b1), via Ahi*Bhi + Alo*Bhi + Ahi*Blo.
// Block 128x128, 8 warps (4m x 2n), warp tile 32x64, k-chunk 16 fp32.
// Double-buffered smem -> ONE __syncthreads per k-chunk.
#define APITCH 24   // bf16 elements per smem row (16 data + 8 pad = 48B)

__global__ __launch_bounds__(256, 2) void k_gemm1(const float* __restrict__ x,
                                                  const float* __restrict__ b1) {
    __shared__ __nv_bfloat16 sAhi[2][128 * APITCH];
    __shared__ __nv_bfloat16 sAlo[2][128 * APITCH];
    __shared__ __nv_bfloat16 sBhi[2][128 * APITCH];
    __shared__ __nv_bfloat16 sBlo[2][128 * APITCH];

    int t = threadIdx.x;
    int lane = t & 31;
    int wid = t >> 5;
    int m0 = blockIdx.y * 128;
    int n0 = blockIdx.x * 128;
    int wm = (wid & 3) * 32;
    int wn = (wid >> 2) * 64;

    float acc[2][8][4];
    #pragma unroll
    for (int i = 0; i < 2; i++)
        #pragma unroll
        for (int j = 0; j < 8; j++)
            #pragma unroll
            for (int q = 0; q < 4; q++) acc[i][j][q] = 0.f;

    int lrow = t >> 1;            // 0..127
    int lq   = (t & 1) << 3;      // 0 or 8
    int grow = m0 + lrow;

    uint32_t aHi[2] = {sptr(sAhi[0]), sptr(sAhi[1])};
    uint32_t aLo[2] = {sptr(sAlo[0]), sptr(sAlo[1])};
    uint32_t bHi[2] = {sptr(sBhi[0]), sptr(sBhi[1])};
    uint32_t bLo[2] = {sptr(sBlo[0]), sptr(sBlo[1])};

    // ldmatrix coordinates (non-trans x4 for both A and B)
    int a_r = (lane & 15);
    int a_c = (lane >> 4) << 3;
    int b_r = (lane & 7) + ((lane >> 4) << 3);
    int b_c = ((lane >> 3) & 1) << 3;

    float4 pA0, pA1;
    uint4 pBh, pBl;

    auto ldA = [&](int kc) {
        const float* Ab = (kc < 8) ? (x + kc * 16) : (g_hn1 + (kc - 8) * 16);
        if (grow < N_DST1) {
            const float* p = Ab + (size_t)grow * IN_F + lq;
            pA0 = *(const float4*)p;
            pA1 = *(const float4*)(p + 4);
        } else {
            pA0 = make_float4(0.f, 0.f, 0.f, 0.f);
            pA1 = make_float4(0.f, 0.f, 0.f, 0.f);
        }
    };
    auto ldB = [&](int kc) {
        size_t off = (size_t)(n0 + lrow) * 256 + kc * 16 + lq;
        pBh = *(const uint4*)(g_Bhi + off);
        pBl = *(const uint4*)(g_Blo + off);
    };
    auto sts = [&](int buf) {
        uint4 hi, lo;
        split8(pA0, pA1, hi, lo);
        *(uint4*)&sAhi[buf][lrow * APITCH + lq] = hi;
        *(uint4*)&sAlo[buf][lrow * APITCH + lq] = lo;
        *(uint4*)&sBhi[buf][lrow * APITCH + lq] = pBh;
        *(uint4*)&sBlo[buf][lrow * APITCH + lq] = pBl;
    };
    auto pass = [&](uint32_t abase, uint32_t bbase) {
        uint32_t a[2][4];
        #pragma unroll
        for (int mf = 0; mf < 2; mf++)
            ldm_x4(a[mf], abase + ((wm + mf * 16 + a_r) * APITCH + a_c) * 2);
        #pragma unroll
        for (int pair = 0; pair < 4; pair++) {
            uint32_t bb[4];
            ldm_x4(bb, bbase + ((wn + pair * 16 + b_r) * APITCH + b_c) * 2);
            #pragma unroll
            for (int mf = 0; mf < 2; mf++) {
                mma16816(acc[mf][pair * 2],     a[mf], bb[0], bb[1]);
                mma16816(acc[mf][pair * 2 + 1], a[mf], bb[2], bb[3]);
            }
        }
    };

    ldA(0);
    ldB(0);
    sts(0);
    __syncthreads();

    for (int kc = 0; kc < 16; kc++) {
        int cb = kc & 1;
        if (kc < 15) { ldA(kc + 1); ldB(kc + 1); }
        pass(aHi[cb], bHi[cb]);
        pass(aLo[cb], bHi[cb]);
        pass(aHi[cb], bLo[cb]);
        if (kc < 15) sts(cb ^ 1);
        __syncthreads();
    }

    // epilogue: bias + relu
    #pragma unroll
    for (int mf = 0; mf < 2; mf++) {
        int gr0 = m0 + wm + mf * 16 + (lane >> 2);
        int gr1 = gr0 + 8;
        #pragma unroll
        for (int nf = 0; nf < 8; nf++) {
            int gn = n0 + wn + nf * 8 + ((lane & 3) << 1);
            float bx = b1[gn];
            float by = b1[gn + 1];
            float* d = acc[mf][nf];
            if (gr0 < N_DST1)
                *(float2*)&g_h[(size_t)gr0 * H_F + gn] =
                    make_float2(fmaxf(d[0] + bx, 0.f), fmaxf(d[1] + by, 0.f));
            if (gr1 < N_DST1)
                *(float2*)&g_h[(size_t)gr1 * H_F + gn] =
                    make_float2(fmaxf(d[2] + bx, 0.f), fmaxf(d[3] + by, 0.f));
        }
    }
}

// ---------------- layer-2 GEMM + count-rezero tail ----------------
__global__ __launch_bounds__(256) void k_gemm2(const float* __restrict__ Ws2,
                                               const float* __restrict__ Wn2,
                                               const float* __restrict__ b2,
                                               float* __restrict__ out) {
    __shared__ float As[32][128];
    __shared__ float Bs[32][48];
    int t = threadIdx.x;
    int m0 = blockIdx.x * 128;
    int r0 = (t >> 3) * 4;
    int c0 = (t & 7) * 6;

    unsigned long long acc[4][3];
    #pragma unroll
    for (int i = 0; i < 4; i++)
        #pragma unroll
        for (int j = 0; j < 3; j++) acc[i][j] = 0ull;

    for (int kt = 0; kt < 16; kt++) {
        const float* Ab = (kt < 8) ? g_h : g_hn2;
        const float* Bb = (kt < 8) ? Ws2 : Wn2;
        int koff = (kt < 8) ? kt * 32 : (kt - 8) * 32;

        {
            int row = t >> 1;
            int grow = m0 + row;
            #pragma unroll
            for (int j = 0; j < 4; j++) {
                int kq = (t & 1) * 16 + j * 4;
                float4 v = make_float4(0.f, 0.f, 0.f, 0.f);
                if (grow < N_DST2) v = *(const float4*)(Ab + (size_t)grow * H_F + koff + kq);
                As[kq + 0][row] = v.x;
                As[kq + 1][row] = v.y;
                As[kq + 2][row] = v.z;
                As[kq + 3][row] = v.w;
            }
        }
        for (int l = t; l < 32 * N_CLS; l += 256) {
            int k = l / N_CLS;
            int c = l - k * N_CLS;
            Bs[k][c] = Bb[(size_t)(koff + k) * N_CLS + c];
        }
        __syncthreads();
        #pragma unroll
        for (int k = 0; k < 32; k++) {
            float4 a = *(const float4*)&As[k][r0];
            float av[4] = {a.x, a.y, a.z, a.w};
            unsigned long long bp[3];
            bp[0] = *(const unsigned long long*)&Bs[k][c0];
            bp[1] = *(const unsigned long long*)&Bs[k][c0 + 2];
            bp[2] = *(const unsigned long long*)&Bs[k][c0 + 4];
            #pragma unroll
            for (int i = 0; i < 4; i++) {
                unsigned long long ad = dup2(av[i]);
                #pragma unroll
                for (int j = 0; j < 3; j++) fma2(acc[i][j], ad, bp[j]);
            }
        }
        __syncthreads();
    }

    #pragma unroll
    for (int i = 0; i < 4; i++) {
        int row = m0 + r0 + i;
        if (row < N_DST2) {
            #pragma unroll
            for (int j = 0; j < 3; j++) {
                float2 v = unpack2(acc[i][j]);
                int c = c0 + 2 * j;
                if (c < N_CLS)     out[(size_t)row * N_CLS + c]     = v.x + b2[c];
                if (c + 1 < N_CLS) out[(size_t)row * N_CLS + c + 1] = v.y + b2[c + 1];
            }
        }
    }

    // rezero counts for the next graph replay (grid-stride)
    int stride = gridDim.x * blockDim.x;
    for (int i = blockIdx.x * blockDim.x + t; i < N_DST1; i += stride) g_cnt1[i] = 0;
    for (int i = blockIdx.x * blockDim.x + t; i < N_DST2; i += stride) g_cnt2[i] = 0;
}

// ---------------- launch ----------------
extern "C" void kernel_launch(void* const* d_in, const int* in_sizes, int n_in,
                              void* d_out, int out_size) {
    const float* x   = (const float*)d_in[0];
    const float* Ws1 = (const float*)d_in[1];
    const float* Wn1 = (const float*)d_in[2];
    const float* b1  = (const float*)d_in[3];
    const float* Ws2 = (const float*)d_in[4];
    const float* Wn2 = (const float*)d_in[5];
    const float* b2  = (const float*)d_in[6];
    const int* src1  = (const int*)d_in[7];
    const int* dst1  = (const int*)d_in[8];
    const int* src2  = (const int*)d_in[9];
    const int* dst2  = (const int*)d_in[10];
    float* out = (float*)d_out;

    k_count_split<<<(E1 + 255) / 256, 256>>>(dst1, dst2, Ws1, Wn1);   // 0
    k_scanA<<<NB1 + NB2, 1024>>>();                                   // 1
    k_scanB<<<1, 256>>>();                                            // 2
    k_scanC<<<NB1 + NB2, 1024>>>();                                   // 3
    k_fill<<<(E1 + 255) / 256, 256>>>(src1, dst1, src2, dst2);        // 4
    k_agg1<<<(N_DST1 * 32 + 255) / 256, 256>>>((const float4*)x);     // 5  <- ncu -s 5 -c 1
    dim3 g1(2, (N_DST1 + 127) / 128);
    k_gemm1<<<g1, 256>>>(x, b1);                                      // 6
    k_agg2<<<(N_DST2 * 32 + 255) / 256, 256>>>();                     // 7
    k_gemm2<<<(N_DST2 + 127) / 128, 256>>>(Ws2, Wn2, b2, out);        // 8
}